// round 1
// baseline (speedup 1.0000x reference)
#include <cuda_runtime.h>

// Jacobi 2D 5-point stencil, edge-clamped padding, 10 steps.
// grid: (8, 4, 1024, 1024) fp32 -> 32 planes of 1024x1024.
//
// Step i: out = u + ALPHA * (left + right + up + down - 4*u)
// with neighbors clamped at the plane edges (pad mode='edge').

#define ALPHA 0.25f
#define H 1024
#define W 1024
#define PLANES 32              // 8 * 4
#define PLANE_ELEMS (H * W)
#define TOTAL_ELEMS (PLANES * PLANE_ELEMS)

// Ping-pong scratch (allocation-free rule: __device__ globals only).
__device__ float g_bufA[TOTAL_ELEMS];
__device__ float g_bufB[TOTAL_ELEMS];

// One block per (row, plane). 256 threads, each thread computes a float4
// (4 contiguous x positions). W=1024 -> 256 float4 per row.
__global__ __launch_bounds__(256) void jacobi_step_kernel(
    const float* __restrict__ in, float* __restrict__ out)
{
    const int v     = threadIdx.x;          // vector index 0..255
    const int y     = blockIdx.x;           // row 0..1023
    const int plane = blockIdx.y;           // 0..31

    const float* p = in + (size_t)plane * PLANE_ELEMS;

    const int yu = (y == 0)     ? 0       : y - 1;
    const int yd = (y == H - 1) ? H - 1   : y + 1;

    const float4* rowc = (const float4*)(p + (size_t)y  * W);
    const float4* rowu = (const float4*)(p + (size_t)yu * W);
    const float4* rowd = (const float4*)(p + (size_t)yd * W);

    const float4 c  = rowc[v];
    const float4 up = rowu[v];
    const float4 dn = rowd[v];

    // Horizontal neighbors across float4 boundaries, clamped at columns 0 / W-1.
    const float leftw  = (v == 0)       ? c.x : ((const float*)rowc)[4 * v - 1];
    const float rightx = (v == 255)     ? c.w : ((const float*)rowc)[4 * v + 4];

    float4 o;
    o.x = fmaf(ALPHA, (leftw + c.y + up.x + dn.x - 4.0f * c.x), c.x);
    o.y = fmaf(ALPHA, (c.x   + c.z + up.y + dn.y - 4.0f * c.y), c.y);
    o.z = fmaf(ALPHA, (c.y   + c.w + up.z + dn.z - 4.0f * c.z), c.z);
    o.w = fmaf(ALPHA, (c.z   + rightx + up.w + dn.w - 4.0f * c.w), c.w);

    float4* orow = (float4*)(out + (size_t)plane * PLANE_ELEMS + (size_t)y * W);
    orow[v] = o;
}

extern "C" void kernel_launch(void* const* d_in, const int* in_sizes, int n_in,
                              void* d_out, int out_size)
{
    const float* in = (const float*)d_in[0];
    float* out = (float*)d_out;

    float* bufA = nullptr;
    float* bufB = nullptr;
    cudaGetSymbolAddress((void**)&bufA, g_bufA);
    cudaGetSymbolAddress((void**)&bufB, g_bufB);

    dim3 grid(H, PLANES);
    dim3 block(256);

    // 10 steps: in -> A -> B -> A -> B -> A -> B -> A -> B -> A -> out
    const float* src = in;
    for (int step = 0; step < 10; ++step) {
        float* dst;
        if (step == 9)          dst = out;
        else if ((step & 1) == 0) dst = bufA;
        else                     dst = bufB;

        jacobi_step_kernel<<<grid, block>>>(src, dst);
        src = dst;
    }
}

// round 4
// speedup vs baseline: 1.7823x; 1.7823x over previous
#include <cuda_runtime.h>

// 10-step Jacobi (5-point, edge-clamped) on 32 planes of 1024x1024 fp32.
// Temporal fusion: 5 steps per kernel launch, 2 launches.
// Overlapped (trapezoid) tiling: each block computes a 112x38 output tile
// from a 128x48 static-shared region (halo 8 in x, 5 in y). Horizontal
// neighbors via warp shuffle, vertical via a rolling 3-row register
// window. Double-buffered static smem (48 KB, no opt-in / no
// cudaFuncSetAttribute), 1 sync per step.

#define ALPHA 0.25f
#define W 1024
#define H 1024
#define PLANES 32
#define PLANE_ELEMS (H * W)
#define TOTAL_ELEMS (PLANES * PLANE_ELEMS)

#define K 5              // fused steps per launch
#define HX 8             // x halo (float4/warp aligned)
#define HY 5             // y halo (= K)
#define RW 128           // region width in floats = 32 float4 lanes
#define RH 48            // region height in rows
#define TX (RW - 2*HX)   // 112 output tile width
#define TY (RH - 2*HY)   // 38  output tile height
#define NWARP 8
#define ROWS_PER_WARP (RH / NWARP)   // 6
#define THREADS 256

#define TILES_X 10       // ceil(1024/112)
#define TILES_Y 27       // ceil(1024/38)

// Intermediate full-grid buffer between the two fused launches.
__device__ float g_mid[TOTAL_ELEMS];

__global__ __launch_bounds__(THREADS, 2) void jacobi_fused5(
    const float* __restrict__ in, float* __restrict__ out)
{
    __shared__ float sm[2][RH * RW];   // 2 * 48 * 128 * 4 = 49152 B (static)

    const int lane  = threadIdx.x & 31;
    const int warp  = threadIdx.x >> 5;
    const int x0    = blockIdx.x * TX;
    const int y0    = blockIdx.y * TY;
    const int plane = blockIdx.z;

    const int gxb = x0 - HX + 4 * lane;   // global x of this lane's float4 base

    const float* pin  = in  + (size_t)plane * PLANE_ELEMS;
    float*       pout = out + (size_t)plane * PLANE_ELEMS;

    const int r0 = warp * ROWS_PER_WARP;
    const int r1 = r0 + ROWS_PER_WARP;

    // ---- Load region into sm[0] (coordinates clamped to the plane) ----
    #pragma unroll
    for (int r = r0; r < r1; ++r) {
        int gy = y0 - HY + r;
        gy = gy < 0 ? 0 : (gy > H - 1 ? H - 1 : gy);
        const float* row = pin + (size_t)gy * W;
        float4 v;
        if (gxb >= 0 && gxb + 3 < W) {
            v = *(const float4*)(row + gxb);
        } else {
            int xa = gxb + 0; xa = xa < 0 ? 0 : (xa > W - 1 ? W - 1 : xa);
            int xb = gxb + 1; xb = xb < 0 ? 0 : (xb > W - 1 ? W - 1 : xb);
            int xc = gxb + 2; xc = xc < 0 ? 0 : (xc > W - 1 ? W - 1 : xc);
            int xd = gxb + 3; xd = xd < 0 ? 0 : (xd > W - 1 ? W - 1 : xd);
            v.x = row[xa]; v.y = row[xb]; v.z = row[xc]; v.w = row[xd];
        }
        *(float4*)(&sm[0][r * RW + 4 * lane]) = v;
    }
    __syncthreads();

    const bool atL = (gxb == 0);          // float4 starts at global col 0
    const bool atR = (gxb + 3 == W - 1);  // float4 ends at global col W-1

    #pragma unroll
    for (int s = 0; s < K; ++s) {
        const float* rd = sm[s & 1];
        float*       wr = sm[(s & 1) ^ 1];

        float4 cur  = *(const float4*)(rd + r0 * RW + 4 * lane);
        float4 prev = (r0 > 0) ? *(const float4*)(rd + (r0 - 1) * RW + 4 * lane) : cur;

        #pragma unroll
        for (int r = r0; r < r1; ++r) {
            float4 next = (r + 1 < RH) ? *(const float4*)(rd + (r + 1) * RW + 4 * lane) : cur;

            const int gy = y0 - HY + r;
            const float4 up = (gy == 0)     ? cur : prev;
            const float4 dn = (gy == H - 1) ? cur : next;

            // Horizontal neighbors across float4 boundaries via shuffle.
            const float lw = __shfl_up_sync(0xffffffffu, cur.w, 1);
            const float rx = __shfl_down_sync(0xffffffffu, cur.x, 1);
            const float L = (lane == 0 || atL)  ? cur.x : lw;
            const float R = (lane == 31 || atR) ? cur.w : rx;

            float4 o;
            o.x = fmaf(ALPHA, L     + cur.y + up.x + dn.x - 4.0f * cur.x, cur.x);
            o.y = fmaf(ALPHA, cur.x + cur.z + up.y + dn.y - 4.0f * cur.y, cur.y);
            o.z = fmaf(ALPHA, cur.y + cur.w + up.z + dn.z - 4.0f * cur.z, cur.z);
            o.w = fmaf(ALPHA, cur.z + R     + up.w + dn.w - 4.0f * cur.w, cur.w);

            *(float4*)(wr + r * RW + 4 * lane) = o;

            prev = cur;
            cur = next;
        }
        __syncthreads();
    }

    // ---- Write output tile (sm[K & 1] holds the K-step result) ----
    const float* res = sm[K & 1];
    if (gxb >= x0 && gxb < x0 + TX && gxb < W) {
        const int rs = r0 > HY ? r0 : HY;
        const int re = r1 < HY + TY ? r1 : HY + TY;
        for (int r = rs; r < re; ++r) {
            const int gy = y0 - HY + r;
            if (gy < H) {
                *(float4*)(pout + (size_t)gy * W + gxb) =
                    *(const float4*)(res + r * RW + 4 * lane);
            }
        }
    }
}

extern "C" void kernel_launch(void* const* d_in, const int* in_sizes, int n_in,
                              void* d_out, int out_size)
{
    const float* in = (const float*)d_in[0];
    float* out = (float*)d_out;

    float* mid = nullptr;
    cudaGetSymbolAddress((void**)&mid, g_mid);

    dim3 grid(TILES_X, TILES_Y, PLANES);
    dim3 block(THREADS);

    jacobi_fused5<<<grid, block>>>(in, mid);
    jacobi_fused5<<<grid, block>>>(mid, out);
}